// round 2
// baseline (speedup 1.0000x reference)
#include <cuda_runtime.h>
#include <cstdint>

// Problem constants (fixed by the dataset)
#define BQ    128
#define TT    512
#define CC    1024
#define LL    64
#define SS    129           // 2*LL + 1 extended states
#define BLANKC 1023
#define EPSF  1e-7f
#define JPER  5             // states per lane (26 lanes * 5 = 130 >= 129)
#define PF    8             // prefetch depth (software pipeline)
#define EF_TARGET 226       // rescale target: warp max in [2^99, 2^100)

__device__ __forceinline__ float pick5(const float a0, const float a1, const float a2,
                                       const float a3, const float a4, int j) {
    float r = a0;
    if (j == 1) r = a1;
    else if (j == 2) r = a2;
    else if (j == 3) r = a3;
    else if (j == 4) r = a4;
    return r;
}

__global__ __launch_bounds__(32, 1)
void ctc_fwd_kernel(const int* __restrict__ y_true,
                    const float* __restrict__ y_pred,
                    const int* __restrict__ input_length,
                    const int* __restrict__ label_length,
                    float* __restrict__ out)
{
    const int b    = blockIdx.x;
    const int lane = threadIdx.x;
    const unsigned FULL = 0xffffffffu;

    const int Tb = input_length[b];          // uniform across warp
    const int Ll = label_length[b];
    const int Sb = 2 * Ll + 1;

    const int*   lrow  = y_true + b * LL;
    const float* prow0 = y_pred + (size_t)b * TT * CC;

    // Per-lane static state metadata: states s = lane*5 + j
    int   lab[JPER];
    float skipf[JPER];
    float validf[JPER];
#pragma unroll
    for (int j = 0; j < JPER; j++) {
        const int s = lane * JPER + j;
        const bool inrange = (s < SS);
        const bool v = inrange && (s < Sb);
        int  lb = BLANKC;
        bool sk = false;
        if (inrange && (s & 1)) {
            lb = lrow[s >> 1];
            if (s >= 3) sk = (lb != lrow[(s >> 1) - 1]);
        }
        lab[j]    = lb;
        skipf[j]  = sk ? 1.0f : 0.0f;
        validf[j] = v ? 1.0f : 0.0f;
    }

    // alpha init: linear domain, mass 1 at s=0 (reference's virtual alpha_{-1})
    float a0 = 0.f, a1r = 0.f, a2r = 0.f, a3r = 0.f, a4r = 0.f;
    if (lane == 0) a0 = 1.0f;

    // Software-pipelined prefetch of gathered probabilities, PF steps deep
    float pre[PF][JPER];
#pragma unroll
    for (int k = 0; k < PF; k++) {
        const float* pr = prow0 + (size_t)k * CC;
#pragma unroll
        for (int j = 0; j < JPER; j++) pre[k][j] = __ldg(pr + lab[j]);
    }

    int esum = 0;   // accumulated power-of-two rescale exponent (exact)
                    // invariant: alpha_true = alpha_stored * 2^esum

    for (int tb = 0; tb < Tb; tb += PF) {
#pragma unroll
        for (int k = 0; k < PF; k++) {
            const int t = tb + k;
            if (t < Tb) {
                // halo from lane-1: its states j=3 (s-2) and j=4 (s-1) of my s=5*lane
                float h3 = __shfl_up_sync(FULL, a3r, 1);
                float h4 = __shfl_up_sync(FULL, a4r, 1);
                if (lane == 0) { h3 = 0.f; h4 = 0.f; }

                const float e0 = validf[0] * (pre[k][0] + EPSF);
                const float e1 = validf[1] * (pre[k][1] + EPSF);
                const float e2 = validf[2] * (pre[k][2] + EPSF);
                const float e3 = validf[3] * (pre[k][3] + EPSF);
                const float e4 = validf[4] * (pre[k][4] + EPSF);

                const float n0 = (a0 + h4  + skipf[0] * h3 ) * e0;
                const float n1 = (a1r + a0 + skipf[1] * h4 ) * e1;
                const float n2 = (a2r + a1r + skipf[2] * a0 ) * e2;
                const float n3 = (a3r + a2r + skipf[3] * a1r) * e3;
                const float n4 = (a4r + a3r + skipf[4] * a2r) * e4;
                a0 = n0; a1r = n1; a2r = n2; a3r = n3; a4r = n4;
            }

            // issue gather loads for step t+PF (independent of alpha chain)
            const int tn = t + PF;
            if (tn < TT) {
                const float* pr = prow0 + (size_t)tn * CC;
#pragma unroll
                for (int j = 0; j < JPER; j++) pre[k][j] = __ldg(pr + lab[j]);
            }

            // Exact power-of-two rescale every 4 steps.
            // Anchor warp max near 2^99 so states up to ~2^-225 below the max
            // stay in the fp32 NORMAL range (full mantissa precision for the
            // end states, which sit ~100-140 nats below the warp max).
            if ((k & 3) == 3) {
                float m = fmaxf(fmaxf(fmaxf(a0, a1r), fmaxf(a2r, a3r)), a4r);
                unsigned mu = __reduce_max_sync(FULL, __float_as_uint(m));
                if (mu != 0u) {
                    const int ef = (int)(mu >> 23);            // biased exponent of max
                    int kk = EF_TARGET - ef;                   // desired shift
                    kk = kk > 127 ? 127 : (kk < -126 ? -126 : kk);
                    const float sc = __int_as_float((unsigned)(127 + kk) << 23); // 2^kk exact
                    esum -= kk;
                    a0 *= sc; a1r *= sc; a2r *= sc; a3r *= sc; a4r *= sc;
                }
            }
        }
    }

    // Final: loss = -( log(alpha[2Ll] + alpha[2Ll-1]) + esum*ln2 )
    const int se0 = 2 * Ll;        // final blank state
    const int se1 = 2 * Ll - 1;    // final label state
    const int l0 = se0 / JPER, j0 = se0 % JPER;
    const int l1 = se1 / JPER, j1 = se1 % JPER;

    const float v0 = pick5(a0, a1r, a2r, a3r, a4r, j0);
    const float v1 = pick5(a0, a1r, a2r, a3r, a4r, j1);
    const float fa1 = __shfl_sync(FULL, v0, l0);
    const float fa2 = __shfl_sync(FULL, v1, l1);

    if (lane == 0) {
        const float s = fmaxf(fa1 + fa2, 1e-43f);   // guard against -inf
        const float loss = -(logf(s) + (float)esum * 0.6931471805599453f);
        out[b] = loss;
    }
}

extern "C" void kernel_launch(void* const* d_in, const int* in_sizes, int n_in,
                              void* d_out, int out_size)
{
    const int*   y_true       = (const int*)  d_in[0];   // [B,L] int32
    const float* y_pred       = (const float*)d_in[1];   // [B,T,C] f32
    const int*   input_length = (const int*)  d_in[2];   // [B,1] int32
    const int*   label_length = (const int*)  d_in[3];   // [B,1] int32
    float*       out          = (float*)d_out;           // [B,1] f32

    ctc_fwd_kernel<<<BQ, 32>>>(y_true, y_pred, input_length, label_length, out);
}